// round 2
// baseline (speedup 1.0000x reference)
#include <cuda_runtime.h>

// Problem constants (fixed by setup_inputs): frames=64, height=23, width=24,
// hidden=1152, interval=1.
constexpr int FRAMES  = 64;
constexpr int H       = 23;
constexpr int W       = 24;
constexpr int HIDDEN  = 1152;
constexpr int TPF     = H * W;          // 552 tokens per frame
constexpr int TOTAL   = FRAMES * TPF;   // 35328
constexpr int VEC4    = HIDDEN / 4;     // 288 float4 per vector
constexpr int PER_LANE = VEC4 / 32;     // 9 float4 per lane
constexpr float EPS   = 1e-8f;

__global__ void __launch_bounds__(256)
simdiff_kernel(const float* __restrict__ x,
               float* __restrict__ out_right,
               float* __restrict__ out_down) {
    const int gwarp = (blockIdx.x * blockDim.x + threadIdx.x) >> 5;
    const int lane  = threadIdx.x & 31;
    if (gwarp >= TOTAL) return;

    const int t = gwarp;
    const int f = t / TPF;
    const int i = t - f * TPF;

    const bool frame_valid = (f < FRAMES - 1);        // interval = 1
    const bool r_valid = frame_valid && (i < TPF - 1);
    const bool d_valid = frame_valid && (i < TPF - W);

    if (!frame_valid) {
        if (lane == 0) { out_right[t] = -1.0f; out_down[t] = -1.0f; }
        return;
    }

    const float4* __restrict__ a  = (const float4*)(x + (size_t)t * HIDDEN);
    const float4* __restrict__ br = (const float4*)(x + (size_t)(t + TPF + 1) * HIDDEN);
    const float4* __restrict__ bd = (const float4*)(x + (size_t)(t + TPF + W) * HIDDEN);

    float na = 0.f, nbr = 0.f, nbd = 0.f, dr = 0.f, dd = 0.f;

#pragma unroll
    for (int k = 0; k < PER_LANE; k++) {
        const int idx = lane + 32 * k;
        float4 av = a[idx];
        na = fmaf(av.x, av.x, na);
        na = fmaf(av.y, av.y, na);
        na = fmaf(av.z, av.z, na);
        na = fmaf(av.w, av.w, na);
        if (r_valid) {
            float4 bv = br[idx];
            dr  = fmaf(av.x, bv.x, dr);
            dr  = fmaf(av.y, bv.y, dr);
            dr  = fmaf(av.z, bv.z, dr);
            dr  = fmaf(av.w, bv.w, dr);
            nbr = fmaf(bv.x, bv.x, nbr);
            nbr = fmaf(bv.y, bv.y, nbr);
            nbr = fmaf(bv.z, bv.z, nbr);
            nbr = fmaf(bv.w, bv.w, nbr);
        }
        if (d_valid) {
            float4 bv = bd[idx];
            dd  = fmaf(av.x, bv.x, dd);
            dd  = fmaf(av.y, bv.y, dd);
            dd  = fmaf(av.z, bv.z, dd);
            dd  = fmaf(av.w, bv.w, dd);
            nbd = fmaf(bv.x, bv.x, nbd);
            nbd = fmaf(bv.y, bv.y, nbd);
            nbd = fmaf(bv.z, bv.z, nbd);
            nbd = fmaf(bv.w, bv.w, nbd);
        }
    }

    // warp reduction of the 5 partial sums
#pragma unroll
    for (int off = 16; off > 0; off >>= 1) {
        na  += __shfl_xor_sync(0xFFFFFFFFu, na,  off);
        nbr += __shfl_xor_sync(0xFFFFFFFFu, nbr, off);
        nbd += __shfl_xor_sync(0xFFFFFFFFu, nbd, off);
        dr  += __shfl_xor_sync(0xFFFFFFFFu, dr,  off);
        dd  += __shfl_xor_sync(0xFFFFFFFFu, dd,  off);
    }

    if (lane == 0) {
        float norm_a = fmaxf(sqrtf(na), EPS);
        float rv = -1.0f, dv = -1.0f;
        if (r_valid) rv = dr / (norm_a * fmaxf(sqrtf(nbr), EPS));
        if (d_valid) dv = dd / (norm_a * fmaxf(sqrtf(nbd), EPS));
        out_right[t] = rv;
        out_down[t]  = dv;
    }
}

extern "C" void kernel_launch(void* const* d_in, const int* in_sizes, int n_in,
                              void* d_out, int out_size) {
    const float* x = (const float*)d_in[0];
    float* out = (float*)d_out;
    float* out_right = out;
    float* out_down  = out + TOTAL;

    const int warps_per_block = 256 / 32;                // 8
    const int blocks = (TOTAL + warps_per_block - 1) / warps_per_block;  // 4416
    simdiff_kernel<<<blocks, 256>>>(x, out_right, out_down);
}